// round 15
// baseline (speedup 1.0000x reference)
#include <cuda_runtime.h>
#include <cstdint>

#define BATCH 8
#define NCAND 2535   // 3*13*13 + 3*26*26
#define TOPK 300
#define NPAD 4096

typedef unsigned long long u64;

__device__ __forceinline__ u64 pack2(float x, float y) {
    u64 r;
    asm("mov.b64 %0, {%1, %2};" : "=l"(r)
        : "r"(__float_as_uint(x)), "r"(__float_as_uint(y)));
    return r;
}
__device__ __forceinline__ void unpack2(u64 v, float& x, float& y) {
    unsigned a, b;
    asm("mov.b64 {%0, %1}, %2;" : "=r"(a), "=r"(b) : "l"(v));
    x = __uint_as_float(a); y = __uint_as_float(b);
}
__device__ __forceinline__ u64 fma2(u64 a, u64 b, u64 c) {
    u64 d;
    asm("fma.rn.f32x2 %0, %1, %2, %3;" : "=l"(d) : "l"(a), "l"(b), "l"(c));
    return d;
}
__device__ __forceinline__ unsigned smem_u32(const void* p) {
    return (unsigned)__cvta_generic_to_shared(p);
}
__device__ __forceinline__ void cp_async16(unsigned dst, const void* src, bool valid) {
    int sz = valid ? 16 : 0;
    asm volatile("cp.async.ca.shared.global [%0], [%1], 16, %2;\n"
                 :: "r"(dst), "l"(src), "r"(sz) : "memory");
}
__device__ __forceinline__ void cp_commit() {
    asm volatile("cp.async.commit_group;\n" ::: "memory");
}
__device__ __forceinline__ void cp_wait0() {
    asm volatile("cp.async.wait_group 0;\n" ::: "memory");
}

// ---------------- scratch (device globals; no allocation) ----------------
__device__ float g_act1[32  * BATCH * 208 * 208];
__device__ float g_act2[64  * BATCH * 104 * 104];
__device__ float g_act3[128 * BATCH * 52  * 52];
__device__ float g_act4[256 * BATCH * 26  * 26];
__device__ float g_act5[512 * BATCH * 13  * 13];
__device__ float g_feat1[255 * BATCH * 13 * 13];
__device__ float g_feat2[255 * BATCH * 26 * 26];
__device__ float g_part[4 * 512 * 5408];          // split-K partials
__device__ float g_cand[BATCH * NCAND * 8];

// ---------------- fused im2col GEMM: 3x3 stride-2 conv as implicit GEMM ----
// C[M][N] = W[M][K] * im2col(act)[K][N], K = CIN*9, N = BATCH*HOUT*WOUT.
// BN=128, BK=16, 8x8 f32x2 micro-tile.
// REORD: virtual k-order k' = (ky*3+kx)*CIN + c. A 16-k' tile has constant
// (ky,kx) -> one predicate per tile, B loads stride CSTR (no div/mod).
// A is read through a per-block smem index table (s_pk[k'] = c*9+t), so the
// ORIGINAL weight tensor is used directly -- no permute kernel.
// act layout: NCHW ? [B][CIN][HIN][WIN] : [CIN][BATCH][HIN][WIN].
// SK>1 -> partials (no bias) at C[sk][M][N].
template <int M, int N, int K, int BM, int SK, bool LRELU, bool NCHW, bool REORD,
          int CIN, int HIN, int WIN, int HOUT, int WOUT, int THREADS>
__global__ void __launch_bounds__(THREADS, (THREADS == 128 ? 3 : (THREADS == 64 ? 6 : 2)))
gemm9f_kernel(const float* __restrict__ A, const float* __restrict__ act,
              const float* __restrict__ bias, float* __restrict__ C)
{
    constexpr int BN = 128, BK = 16;
    constexpr int TX = BN / 8;
    constexpr int TY = BM / 8;
    static_assert(TX * TY == THREADS, "threads");
    constexpr int CPT = (THREADS < BN) ? (BN / THREADS) : 1;
    constexpr int TPC = (THREADS < BN) ? 1 : (THREADS / BN);
    constexpr int RPT = BK / TPC;
    constexpr int KC = (K % SK == 0) ? (K / SK) : K;
    constexpr int NT_ = (KC + BK - 1) / BK;
    constexpr int P = HOUT * WOUT;
    constexpr int HWIN = HIN * WIN;
    constexpr int AE = BM * BK / THREADS;
    constexpr size_t CSTR = NCHW ? (size_t)HWIN : (size_t)BATCH * HWIN;
    static_assert(!REORD || (CIN % BK == 0 && KC % BK == 0), "reorder alignment");
    constexpr int PKN = REORD ? KC : 1;

    __shared__ __align__(16) float As[2][BK][BM + 4];
    __shared__ __align__(16) float Bs[2][BK][BN];
    __shared__ int s_pk[PKN];

    const int tid = threadIdx.x;
    const int tx  = tid % TX;
    const int ty  = tid / TX;
    const int m0  = blockIdx.y * BM;
    const int n0  = blockIdx.x * BN;
    const int k00 = blockIdx.z * KC;

    // A index table: s_pk[i] = original k for reordered position k00+i
    if (REORD) {
        for (int i = tid; i < KC; i += THREADS) {
            int kg = k00 + i;
            int t  = kg / CIN;
            int c  = kg - t * CIN;
            s_pk[i] = c * 9 + t;
        }
    }

    const int colbase = (CPT > 1) ? tid : (tid % BN);
    const int kofs    = (TPC > 1) ? (tid / BN) : 0;

    int  col_[CPT];
    bool nok_[CPT];
    int  iy0_[CPT], ix0_[CPT];
    size_t base_[CPT];
    #pragma unroll
    for (int c = 0; c < CPT; c++) {
        int col = colbase + c * THREADS;
        col_[c] = col;
        int gn = n0 + col;
        bool ok = (N % BN == 0) || (gn < N);
        nok_[c] = ok;
        int gsafe = ok ? gn : 0;
        int bb = gsafe / P;
        int pp = gsafe - bb * P;
        int oy = pp / WOUT;
        int ox = pp - oy * WOUT;
        iy0_[c] = 2 * oy;
        ix0_[c] = 2 * ox;
        base_[c] = (NCHW ? (size_t)bb * CIN : (size_t)bb) * HWIN;
    }
    if (REORD) __syncthreads();

    float ar[AE];
    float br[CPT][RPT];

    u64 acc[8][4];
    #pragma unroll
    for (int i = 0; i < 8; i++)
        #pragma unroll
        for (int j = 0; j < 4; j++) acc[i][j] = pack2(0.f, 0.f);

    auto gatherB = [&](int kt) {
        if (REORD) {
            const int kg0 = k00 + kt;
            const int t   = kg0 / CIN;
            const int ky  = t / 3;
            const int kx  = t - 3 * ky;
            const int c0  = kg0 - t * CIN;
            #pragma unroll
            for (int c = 0; c < CPT; c++) {
                const int iy = iy0_[c] + ky;
                const int ix = ix0_[c] + kx;
                const bool ok = nok_[c] && (iy < HIN) && (ix < WIN);
                const float* bp = act + base_[c] + iy * WIN + ix
                                + (size_t)(c0 + kofs) * CSTR;
                #pragma unroll
                for (int j = 0; j < RPT; j++)
                    br[c][j] = ok ? __ldg(bp + (size_t)(j * TPC) * CSTR) : 0.f;
            }
        } else {
            #pragma unroll
            for (int c = 0; c < CPT; c++) {
                #pragma unroll
                for (int j = 0; j < RPT; j++) {
                    int kl = kt + j * TPC + kofs;
                    int kg = k00 + kl;
                    int ch = kg / 9;
                    int t  = kg - 9 * ch;
                    int ky = t / 3;
                    int kx = t - 3 * ky;
                    int iy = iy0_[c] + ky;
                    int ix = ix0_[c] + kx;
                    bool ok = nok_[c] && (iy < HIN) && (ix < WIN);
                    if (KC % BK != 0) ok = ok && (kl < KC);
                    br[c][j] = ok ? __ldg(act + base_[c] + (size_t)ch * CSTR + iy * WIN + ix) : 0.f;
                }
            }
        }
    };
    auto gatherA = [&](int kt) {
        #pragma unroll
        for (int j = 0; j < AE; j++) {
            int i = tid + j * THREADS;
            int m = i >> 4, kk = i & 15;
            bool ok = true;
            if (M % BM != 0) ok = (m0 + m) < M;
            if (KC % BK != 0) ok = ok && ((kt + kk) < KC);
            int korig = REORD ? s_pk[kt + kk] : (k00 + kt + kk);
            ar[j] = ok ? A[(size_t)(m0 + m) * K + korig] : 0.f;
        }
    };

    gatherB(0);
    gatherA(0);
    #pragma unroll
    for (int c = 0; c < CPT; c++)
        #pragma unroll
        for (int j = 0; j < RPT; j++) Bs[0][j * TPC + kofs][col_[c]] = br[c][j];
    #pragma unroll
    for (int j = 0; j < AE; j++) {
        int i = tid + j * THREADS;
        As[0][i & 15][i >> 4] = ar[j];
    }
    __syncthreads();

    int buf = 0;
    for (int tt = 0; tt < NT_; tt++) {
        const bool has_next = (tt + 1) < NT_;
        if (has_next) {
            gatherB((tt + 1) * BK);
            gatherA((tt + 1) * BK);
        }

        #pragma unroll
        for (int kk = 0; kk < BK; kk++) {
            float4 a0 = *reinterpret_cast<const float4*>(&As[buf][kk][ty * 8]);
            float4 a1 = *reinterpret_cast<const float4*>(&As[buf][kk][ty * 8 + 4]);
            float4 bA = *reinterpret_cast<const float4*>(&Bs[buf][kk][tx * 8]);
            float4 bB = *reinterpret_cast<const float4*>(&Bs[buf][kk][tx * 8 + 4]);
            u64 b01 = pack2(bA.x, bA.y);
            u64 b23 = pack2(bA.z, bA.w);
            u64 b45 = pack2(bB.x, bB.y);
            u64 b67 = pack2(bB.z, bB.w);
            float av[8] = {a0.x, a0.y, a0.z, a0.w, a1.x, a1.y, a1.z, a1.w};
            #pragma unroll
            for (int i = 0; i < 8; i++) {
                u64 ap = pack2(av[i], av[i]);
                acc[i][0] = fma2(ap, b01, acc[i][0]);
                acc[i][1] = fma2(ap, b23, acc[i][1]);
                acc[i][2] = fma2(ap, b45, acc[i][2]);
                acc[i][3] = fma2(ap, b67, acc[i][3]);
            }
        }

        if (has_next) {
            #pragma unroll
            for (int c = 0; c < CPT; c++)
                #pragma unroll
                for (int j = 0; j < RPT; j++) Bs[buf ^ 1][j * TPC + kofs][col_[c]] = br[c][j];
            #pragma unroll
            for (int j = 0; j < AE; j++) {
                int i = tid + j * THREADS;
                As[buf ^ 1][i & 15][i >> 4] = ar[j];
            }
            __syncthreads();
            buf ^= 1;
        }
    }

    float* Cb = (SK == 1) ? C : (C + (size_t)blockIdx.z * M * N);
    #pragma unroll
    for (int i = 0; i < 8; i++) {
        int m = m0 + ty * 8 + i;
        if (M % BM != 0 && m >= M) continue;
        int go = n0 + tx * 8;
        if (N % BN != 0 && go >= N) continue;
        float x0, x1, x2, x3, x4, x5, x6, x7;
        unpack2(acc[i][0], x0, x1);
        unpack2(acc[i][1], x2, x3);
        unpack2(acc[i][2], x4, x5);
        unpack2(acc[i][3], x6, x7);
        if (SK == 1) {
            float bbv = bias[m];
            x0 += bbv; x1 += bbv; x2 += bbv; x3 += bbv;
            x4 += bbv; x5 += bbv; x6 += bbv; x7 += bbv;
            if (LRELU) {
                x0 = x0 > 0.f ? x0 : 0.1f * x0;
                x1 = x1 > 0.f ? x1 : 0.1f * x1;
                x2 = x2 > 0.f ? x2 : 0.1f * x2;
                x3 = x3 > 0.f ? x3 : 0.1f * x3;
                x4 = x4 > 0.f ? x4 : 0.1f * x4;
                x5 = x5 > 0.f ? x5 : 0.1f * x5;
                x6 = x6 > 0.f ? x6 : 0.1f * x6;
                x7 = x7 > 0.f ? x7 : 0.1f * x7;
            }
        }
        *reinterpret_cast<float4*>(&Cb[(size_t)m * N + go])     = make_float4(x0, x1, x2, x3);
        *reinterpret_cast<float4*>(&Cb[(size_t)m * N + go + 4]) = make_float4(x4, x5, x6, x7);
    }
}

// ---------------- plain GEMM (heads): 8x8 tile, cp.async B, double-buffer --
template <int M, int N, int K, int BM, int BN, int SK, int THREADS, bool LRELU>
__global__ void __launch_bounds__(THREADS, (THREADS == 128 ? 4 : 2))
gemm9_kernel(const float* __restrict__ A, const float* __restrict__ B,
             const float* __restrict__ bias, float* __restrict__ C)
{
    constexpr int BK = 16;
    constexpr int TX = BN / 8;
    constexpr int TY = BM / 8;
    static_assert(TX * TY == THREADS, "threads");
    constexpr int KC = K / SK;
    static_assert(KC % BK == 0, "K chunk");
    constexpr int NB4 = BN / 4;
    constexpr int AE  = BM * BK / THREADS;
    constexpr int BE4 = BK * NB4 / THREADS;

    __shared__ __align__(16) float  As[2][BK][BM + 4];
    __shared__ __align__(16) float4 Bs[2][BK][NB4];

    const int tid = threadIdx.x;
    const int tx  = tid % TX;
    const int ty  = tid / TX;
    const int m0  = blockIdx.y * BM;
    const int n0  = blockIdx.x * BN;
    const int k00 = blockIdx.z * KC;

    float ar[AE];

    u64 acc[8][4];
    #pragma unroll
    for (int i = 0; i < 8; i++)
        #pragma unroll
        for (int j = 0; j < 4; j++) acc[i][j] = pack2(0.f, 0.f);

    #pragma unroll
    for (int j = 0; j < BE4; j++) {
        int i = tid + j * THREADS;
        int kk = i / NB4, n4 = i % NB4;
        int gn = n0 + n4 * 4;
        bool ok = (N % BN == 0) || (gn < N);
        const float* src = ok ? &B[(size_t)(k00 + kk) * N + gn] : B;
        cp_async16(smem_u32(&Bs[0][kk][n4]), src, ok);
    }
    cp_commit();
    #pragma unroll
    for (int j = 0; j < AE; j++) {
        int i = tid + j * THREADS;
        int kk = i % BK, m = i / BK;
        float v = 0.f;
        if (M % BM == 0 || (m0 + m) < M) v = A[(size_t)(m0 + m) * K + k00 + kk];
        ar[j] = v;
    }
    #pragma unroll
    for (int j = 0; j < AE; j++) {
        int i = tid + j * THREADS;
        As[0][i % BK][i / BK] = ar[j];
    }
    cp_wait0();
    __syncthreads();

    int buf = 0;
    for (int kt = 0; kt < KC; kt += BK) {
        const bool has_next = (kt + BK) < KC;
        if (has_next) {
            #pragma unroll
            for (int j = 0; j < BE4; j++) {
                int i = tid + j * THREADS;
                int kk = i / NB4, n4 = i % NB4;
                int gn = n0 + n4 * 4;
                bool ok = (N % BN == 0) || (gn < N);
                const float* src = ok ? &B[(size_t)(k00 + kt + BK + kk) * N + gn] : B;
                cp_async16(smem_u32(&Bs[buf ^ 1][kk][n4]), src, ok);
            }
            cp_commit();
            #pragma unroll
            for (int j = 0; j < AE; j++) {
                int i = tid + j * THREADS;
                int kk = i % BK, m = i / BK;
                float v = 0.f;
                if (M % BM == 0 || (m0 + m) < M)
                    v = A[(size_t)(m0 + m) * K + k00 + kt + BK + kk];
                ar[j] = v;
            }
        }

        #pragma unroll
        for (int kk = 0; kk < BK; kk++) {
            float4 a0 = *reinterpret_cast<const float4*>(&As[buf][kk][ty * 8]);
            float4 a1 = *reinterpret_cast<const float4*>(&As[buf][kk][ty * 8 + 4]);
            float4 bA = Bs[buf][kk][tx * 2];
            float4 bB = Bs[buf][kk][tx * 2 + 1];
            u64 b01 = pack2(bA.x, bA.y);
            u64 b23 = pack2(bA.z, bA.w);
            u64 b45 = pack2(bB.x, bB.y);
            u64 b67 = pack2(bB.z, bB.w);
            float av[8] = {a0.x, a0.y, a0.z, a0.w, a1.x, a1.y, a1.z, a1.w};
            #pragma unroll
            for (int i = 0; i < 8; i++) {
                u64 ap = pack2(av[i], av[i]);
                acc[i][0] = fma2(ap, b01, acc[i][0]);
                acc[i][1] = fma2(ap, b23, acc[i][1]);
                acc[i][2] = fma2(ap, b45, acc[i][2]);
                acc[i][3] = fma2(ap, b67, acc[i][3]);
            }
        }

        if (has_next) {
            #pragma unroll
            for (int j = 0; j < AE; j++) {
                int i = tid + j * THREADS;
                As[buf ^ 1][i % BK][i / BK] = ar[j];
            }
            cp_wait0();
            __syncthreads();
            buf ^= 1;
        }
    }

    float* Cb = (SK == 1) ? C : (C + (size_t)blockIdx.z * M * N);
    #pragma unroll
    for (int i = 0; i < 8; i++) {
        int m = m0 + ty * 8 + i;
        if (M % BM != 0 && m >= M) continue;
        int gn = n0 + tx * 8;
        if (N % BN != 0 && gn >= N) continue;
        float x0, x1, x2, x3, x4, x5, x6, x7;
        unpack2(acc[i][0], x0, x1);
        unpack2(acc[i][1], x2, x3);
        unpack2(acc[i][2], x4, x5);
        unpack2(acc[i][3], x6, x7);
        if (SK == 1) {
            float bb = bias[m];
            x0 += bb; x1 += bb; x2 += bb; x3 += bb;
            x4 += bb; x5 += bb; x6 += bb; x7 += bb;
            if (LRELU) {
                x0 = x0 > 0.f ? x0 : 0.1f * x0;
                x1 = x1 > 0.f ? x1 : 0.1f * x1;
                x2 = x2 > 0.f ? x2 : 0.1f * x2;
                x3 = x3 > 0.f ? x3 : 0.1f * x3;
                x4 = x4 > 0.f ? x4 : 0.1f * x4;
                x5 = x5 > 0.f ? x5 : 0.1f * x5;
                x6 = x6 > 0.f ? x6 : 0.1f * x6;
                x7 = x7 > 0.f ? x7 : 0.1f * x7;
            }
        }
        *reinterpret_cast<float4*>(&Cb[(size_t)m * N + gn])     = make_float4(x0, x1, x2, x3);
        *reinterpret_cast<float4*>(&Cb[(size_t)m * N + gn + 4]) = make_float4(x4, x5, x6, x7);
    }
}

// ---------------- split-K reduce: C = sum_sk part + bias (+lrelu) ----------
template <int M, int N, int SK, bool LRELU>
__global__ void reduce_kernel(const float* __restrict__ part,
                              const float* __restrict__ bias,
                              float* __restrict__ C)
{
    int i4 = (blockIdx.x * 256 + threadIdx.x) * 4;
    if (i4 >= M * N) return;
    float4 s = *reinterpret_cast<const float4*>(&part[i4]);
    #pragma unroll
    for (int sk = 1; sk < SK; sk++) {
        float4 p = *reinterpret_cast<const float4*>(&part[(size_t)sk * M * N + i4]);
        s.x += p.x; s.y += p.y; s.z += p.z; s.w += p.w;
    }
    float bb = bias[i4 / N];
    s.x += bb; s.y += bb; s.z += bb; s.w += bb;
    if (LRELU) {
        s.x = s.x > 0.f ? s.x : 0.1f * s.x;
        s.y = s.y > 0.f ? s.y : 0.1f * s.y;
        s.z = s.z > 0.f ? s.z : 0.1f * s.z;
        s.w = s.w > 0.f ? s.w : 0.1f * s.w;
    }
    *reinterpret_cast<float4*>(&C[i4]) = s;
}

// ---------------- decode: feat (CNHW) -> candidate record ----------------
__device__ __forceinline__ float sigmoidf_(float x) { return 1.f / (1.f + expf(-x)); }

__global__ void decode_kernel(const float* __restrict__ feat1,
                              const float* __restrict__ feat2,
                              float* __restrict__ cand)
{
    int idx = blockIdx.x * blockDim.x + threadIdx.x;
    if (idx >= BATCH * NCAND) return;
    int b = idx / NCAND;
    int n = idx - b * NCAND;

    const float A1w[3] = {81.f, 135.f, 344.f}, A1h[3] = {82.f, 169.f, 319.f};
    const float A2w[3] = {10.f, 23.f,  37.f},  A2h[3] = {14.f, 27.f,  58.f};

    const float* base;
    int H, W, a, yy, xx;
    size_t estr;
    float aw, ah;
    if (n < 507) {
        H = 13; W = 13;
        a = n / 169; int r = n - a * 169; yy = r / 13; xx = r - yy * 13;
        aw = A1w[a]; ah = A1h[a];
        estr = (size_t)BATCH * 169;
        base = feat1 + (size_t)(a * 85) * estr + b * 169 + yy * 13 + xx;
    } else {
        int m = n - 507;
        H = 26; W = 26;
        a = m / 676; int r = m - a * 676; yy = r / 26; xx = r - yy * 26;
        aw = A2w[a]; ah = A2h[a];
        estr = (size_t)BATCH * 676;
        base = feat2 + (size_t)(a * 85) * estr + b * 676 + yy * 26 + xx;
    }

    float t0 = base[0];
    float t1 = base[estr];
    float t2 = base[2 * estr];
    float t3 = base[3 * estr];
    float t4 = base[4 * estr];

    float bx = (sigmoidf_(t0) + (float)xx) / (float)W;
    float by = (sigmoidf_(t1) + (float)yy) / (float)H;
    float bw = expf(t2) * aw / 416.f;
    float bh = expf(t3) * ah / 416.f;
    float obj = sigmoidf_(t4);

    float ml = base[5 * estr];
    int lab = 0;
    for (int c = 1; c < 80; c++) {
        float v = base[(5 + c) * estr];
        if (v > ml) { ml = v; lab = c; }
    }
    float cc = sigmoidf_(ml);
    float score = obj * cc;
    if (!(score >= 0.1f)) score = 0.f;

    float* o = cand + (size_t)idx * 8;
    o[0] = (by - bh * 0.5f) * 416.f;
    o[1] = (bx - bw * 0.5f) * 416.f;
    o[2] = (by + bh * 0.5f) * 416.f;
    o[3] = (bx + bw * 0.5f) * 416.f;
    o[4] = obj;
    o[5] = cc;
    o[6] = (float)lab;
    o[7] = score;
}

// ---------------- per-image top-k (bitonic) + greedy NMS ----------------
__global__ void nms_kernel(const float* __restrict__ cand, float* __restrict__ out)
{
    const int b = blockIdx.x;
    const int tid = threadIdx.x; // 1024 threads

    __shared__ u64 keys[NPAD];

    const float* cb = cand + (size_t)b * NCAND * 8;

    for (int i = tid; i < NPAD; i += 1024) {
        u64 k = 0;
        if (i < NCAND) {
            float sc = cb[i * 8 + 7];
            k = ((u64)__float_as_uint(sc) << 32) | (u64)(0xFFFFFFFFu - (unsigned)i);
        }
        keys[i] = k;
    }
    __syncthreads();

    for (int k = 2; k <= NPAD; k <<= 1) {
        for (int j = k >> 1; j > 0; j >>= 1) {
            #pragma unroll 2
            for (int t = tid; t < NPAD / 2; t += 1024) {
                int i = ((t / j) * (j << 1)) + (t % j);
                int l = i + j;
                u64 a = keys[i], c = keys[l];
                bool desc = ((i & k) == 0);
                if (desc ? (a < c) : (a > c)) { keys[i] = c; keys[l] = a; }
            }
            __syncthreads();
        }
    }

    __shared__ float y0s[TOPK], x0s[TOPK], y1s[TOPK], x1s[TOPK], areas[TOPK];
    __shared__ int labs[TOPK];
    __shared__ int sel[TOPK];
    __shared__ unsigned char keep[TOPK];
    if (tid < TOPK) {
        u64 k = keys[tid];
        int ii = (int)(0xFFFFFFFFu - (unsigned)(k & 0xFFFFFFFFu));
        sel[tid] = ii;
        float y0 = cb[ii * 8 + 0], x0 = cb[ii * 8 + 1];
        float y1 = cb[ii * 8 + 2], x1 = cb[ii * 8 + 3];
        y0s[tid] = y0; x0s[tid] = x0; y1s[tid] = y1; x1s[tid] = x1;
        areas[tid] = (y1 - y0) * (x1 - x0);
        labs[tid] = (int)cb[ii * 8 + 6];
        keep[tid] = ((unsigned)(k >> 32) != 0u) ? 1 : 0;
    }
    __syncthreads();

    for (int j = 0; j < TOPK - 1; j++) {
        if (tid > j && tid < TOPK && keep[j] && keep[tid] && labs[tid] == labs[j]) {
            float ty0 = fmaxf(y0s[tid], y0s[j]);
            float tx0 = fmaxf(x0s[tid], x0s[j]);
            float ty1 = fminf(y1s[tid], y1s[j]);
            float tx1 = fminf(x1s[tid], x1s[j]);
            float ih = fmaxf(ty1 - ty0, 0.f);
            float iw = fmaxf(tx1 - tx0, 0.f);
            float inter = ih * iw;
            float iou = inter / (areas[tid] + areas[j] - inter + 1e-9f);
            if (iou > 0.5f) keep[tid] = 0;
        }
        __syncthreads();
    }

    if (tid < TOPK) {
        float* o = out + ((size_t)b * TOPK + tid) * 7;
        if (keep[tid]) {
            int ii = sel[tid];
            o[0] = y0s[tid]; o[1] = x0s[tid]; o[2] = y1s[tid]; o[3] = x1s[tid];
            o[4] = cb[ii * 8 + 4];
            o[5] = cb[ii * 8 + 5];
            o[6] = (float)labs[tid];
        } else {
            #pragma unroll
            for (int k = 0; k < 7; k++) o[k] = 0.f;
        }
    }
}

// ---------------- launch ----------------
static inline int ceil_div(int a, int b) { return (a + b - 1) / b; }

extern "C" void kernel_launch(void* const* d_in, const int* in_sizes, int n_in,
                              void* d_out, int out_size)
{
    (void)in_sizes; (void)n_in; (void)out_size;
    const float* images = (const float*)d_in[0];
    const float* w1 = (const float*)d_in[1];  const float* b1 = (const float*)d_in[2];
    const float* w2 = (const float*)d_in[3];  const float* b2 = (const float*)d_in[4];
    const float* w3 = (const float*)d_in[5];  const float* b3 = (const float*)d_in[6];
    const float* w4 = (const float*)d_in[7];  const float* b4 = (const float*)d_in[8];
    const float* w5 = (const float*)d_in[9];  const float* b5 = (const float*)d_in[10];
    const float* wh1 = (const float*)d_in[11]; const float* bh1 = (const float*)d_in[12];
    const float* wh2 = (const float*)d_in[13]; const float* bh2 = (const float*)d_in[14];
    float* out = (float*)d_out;

    static float *act1 = nullptr, *act2, *act3, *act4, *act5, *feat1, *feat2, *part, *cand;
    if (!act1) {
        cudaGetSymbolAddress((void**)&act1, g_act1);
        cudaGetSymbolAddress((void**)&act2, g_act2);
        cudaGetSymbolAddress((void**)&act3, g_act3);
        cudaGetSymbolAddress((void**)&act4, g_act4);
        cudaGetSymbolAddress((void**)&act5, g_act5);
        cudaGetSymbolAddress((void**)&feat1, g_feat1);
        cudaGetSymbolAddress((void**)&feat2, g_feat2);
        cudaGetSymbolAddress((void**)&part, g_part);
        cudaGetSymbolAddress((void**)&cand, g_cand);
    }

    // --- L1: 3->32, 416->208  (N = 346112, K = 27), BM=32, 64 thr (no reorder)
    gemm9f_kernel<32, 346112, 27, 32, 1, true, true, false, 3, 416, 416, 208, 208, 64>
        <<<dim3(346112 / 128, 1, 1), 64>>>(w1, images, b1, act1);

    // --- L2: 32->64, 208->104 (N = 86528, K = 288), BM=64, reordered (in-kernel)
    gemm9f_kernel<64, 86528, 288, 64, 1, true, false, true, 32, 208, 208, 104, 104, 128>
        <<<dim3(86528 / 128, 1, 1), 128>>>(w2, act1, b2, act2);

    // --- L3: 64->128, 104->52 (N = 21632, K = 576), BM=64, reordered
    gemm9f_kernel<128, 21632, 576, 64, 1, true, false, true, 64, 104, 104, 52, 52, 128>
        <<<dim3(21632 / 128, 2, 1), 128>>>(w3, act2, b3, act3);

    // --- L4: 128->256, 52->26 (N = 5408, K = 1152), BM=64, split-K 2, reordered
    gemm9f_kernel<256, 5408, 1152, 64, 2, false, false, true, 128, 52, 52, 26, 26, 128>
        <<<dim3(ceil_div(5408, 128), 4, 2), 128>>>(w4, act3, b4, part);
    reduce_kernel<256, 5408, 2, true>
        <<<ceil_div(256 * 5408 / 4, 256), 256>>>(part, b4, act4);

    // --- head2: 255 x 5408, K = 256, split-K 2
    gemm9_kernel<255, 5408, 256, 128, 128, 2, 256, false>
        <<<dim3(ceil_div(5408, 128), 2, 2), 256>>>(wh2, act4, bh2, part);
    reduce_kernel<255, 5408, 2, false>
        <<<ceil_div(255 * 5408 / 4 + 1, 256), 256>>>(part, bh2, feat2);

    // --- L5: 256->512, 26->13 (N = 1352, K = 2304), BM=64, split-K 4, reordered
    gemm9f_kernel<512, 1352, 2304, 64, 4, false, false, true, 256, 26, 26, 13, 13, 128>
        <<<dim3(ceil_div(1352, 128), 8, 4), 128>>>(w5, act4, b5, part);
    reduce_kernel<512, 1352, 4, true>
        <<<ceil_div(512 * 1352 / 4, 256), 256>>>(part, b5, act5);

    // --- head1: 255 x 1352, K = 512, split-K 4
    gemm9_kernel<255, 1352, 512, 128, 128, 4, 256, false>
        <<<dim3(ceil_div(1352, 128), 2, 4), 256>>>(wh1, act5, bh1, part);
    reduce_kernel<255, 1352, 4, false>
        <<<ceil_div(255 * 1352 / 4 + 1, 256), 256>>>(part, bh1, feat1);

    // --- decode + nms
    decode_kernel<<<ceil_div(BATCH * NCAND, 256), 256>>>(feat1, feat2, cand);
    nms_kernel<<<BATCH, 1024>>>(cand, out);
}

// round 16
// speedup vs baseline: 1.0510x; 1.0510x over previous
#include <cuda_runtime.h>
#include <cstdint>

#define BATCH 8
#define NCAND 2535   // 3*13*13 + 3*26*26
#define TOPK 300
#define NPAD 4096

typedef unsigned long long u64;

__device__ __forceinline__ u64 pack2(float x, float y) {
    u64 r;
    asm("mov.b64 %0, {%1, %2};" : "=l"(r)
        : "r"(__float_as_uint(x)), "r"(__float_as_uint(y)));
    return r;
}
__device__ __forceinline__ void unpack2(u64 v, float& x, float& y) {
    unsigned a, b;
    asm("mov.b64 {%0, %1}, %2;" : "=r"(a), "=r"(b) : "l"(v));
    x = __uint_as_float(a); y = __uint_as_float(b);
}
__device__ __forceinline__ u64 fma2(u64 a, u64 b, u64 c) {
    u64 d;
    asm("fma.rn.f32x2 %0, %1, %2, %3;" : "=l"(d) : "l"(a), "l"(b), "l"(c));
    return d;
}
__device__ __forceinline__ unsigned smem_u32(const void* p) {
    return (unsigned)__cvta_generic_to_shared(p);
}
__device__ __forceinline__ void cp_async16(unsigned dst, const void* src, bool valid) {
    int sz = valid ? 16 : 0;
    asm volatile("cp.async.ca.shared.global [%0], [%1], 16, %2;\n"
                 :: "r"(dst), "l"(src), "r"(sz) : "memory");
}
__device__ __forceinline__ void cp_commit() {
    asm volatile("cp.async.commit_group;\n" ::: "memory");
}
__device__ __forceinline__ void cp_wait0() {
    asm volatile("cp.async.wait_group 0;\n" ::: "memory");
}

// ---------------- scratch (device globals; no allocation) ----------------
__device__ float g_act1[32  * BATCH * 208 * 208];
__device__ float g_act2[64  * BATCH * 104 * 104];
__device__ float g_act3[128 * BATCH * 52  * 52];
__device__ float g_act4[256 * BATCH * 26  * 26];
__device__ float g_act5[512 * BATCH * 13  * 13];
__device__ float g_feat1[255 * BATCH * 13 * 13];
__device__ float g_feat2[255 * BATCH * 26 * 26];
__device__ float g_part[4 * 512 * 5408];          // split-K partials
__device__ float g_cand[BATCH * NCAND * 8];
__device__ float g_wperm[1566720];                // k-reordered weights L2..L5
// offsets (elements): L2:0  L3:18432  L4:92160  L5:387072

// ---------------- fused weight permute for all 4 layers ------------------
// reorder k = c*9+t  ->  k' = t*CIN + c, segment-dispatched by global index.
__global__ void wperm_all_kernel(const float* __restrict__ w2,
                                 const float* __restrict__ w3,
                                 const float* __restrict__ w4,
                                 const float* __restrict__ w5,
                                 float* __restrict__ wp)
{
    int i = blockIdx.x * 256 + threadIdx.x;
    const float* w;
    int CIN, base;
    if (i < 18432)        { w = w2; CIN = 32;  base = 0; }
    else if (i < 92160)   { w = w3; CIN = 64;  base = 18432; }
    else if (i < 387072)  { w = w4; CIN = 128; base = 92160; }
    else if (i < 1566720) { w = w5; CIN = 256; base = 387072; }
    else return;
    int li = i - base;
    int K = CIN * 9;
    int m = li / K;
    int k = li - m * K;
    int t = k / CIN;
    int c = k - t * CIN;
    wp[i] = w[(size_t)m * K + c * 9 + t];
}

// ---------------- fused im2col GEMM: 3x3 stride-2 conv as implicit GEMM ----
// C[M][N] = W[M][K] * im2col(act)[K][N], K = CIN*9, N = BATCH*HOUT*WOUT.
// BN=128, BK=16, 8x8 f32x2 micro-tile.
// REORD: weights pre-permuted to k = (ky*3+kx)*CIN + c; a 16-k tile then has
// constant (ky,kx) -> one predicate per tile, loads stride CSTR (no div/mod).
// act layout: NCHW ? [B][CIN][HIN][WIN] : [CIN][BATCH][HIN][WIN].
// SK>1 -> partials (no bias) at C[sk][M][N].
template <int M, int N, int K, int BM, int SK, bool LRELU, bool NCHW, bool REORD,
          int CIN, int HIN, int WIN, int HOUT, int WOUT, int THREADS>
__global__ void __launch_bounds__(THREADS, (THREADS == 128 ? 3 : (THREADS == 64 ? 6 : 2)))
gemm9f_kernel(const float* __restrict__ A, const float* __restrict__ act,
              const float* __restrict__ bias, float* __restrict__ C)
{
    constexpr int BN = 128, BK = 16;
    constexpr int TX = BN / 8;
    constexpr int TY = BM / 8;
    static_assert(TX * TY == THREADS, "threads");
    constexpr int CPT = (THREADS < BN) ? (BN / THREADS) : 1;
    constexpr int TPC = (THREADS < BN) ? 1 : (THREADS / BN);
    constexpr int RPT = BK / TPC;
    constexpr int KC = (K % SK == 0) ? (K / SK) : K;
    constexpr int NT_ = (KC + BK - 1) / BK;
    constexpr int P = HOUT * WOUT;
    constexpr int HWIN = HIN * WIN;
    constexpr int AE = BM * BK / THREADS;
    constexpr size_t CSTR = NCHW ? (size_t)HWIN : (size_t)BATCH * HWIN;
    static_assert(!REORD || (CIN % BK == 0 && KC % BK == 0), "reorder alignment");

    __shared__ __align__(16) float As[2][BK][BM + 4];
    __shared__ __align__(16) float Bs[2][BK][BN];

    const int tid = threadIdx.x;
    const int tx  = tid % TX;
    const int ty  = tid / TX;
    const int m0  = blockIdx.y * BM;
    const int n0  = blockIdx.x * BN;
    const int k00 = blockIdx.z * KC;

    const int colbase = (CPT > 1) ? tid : (tid % BN);
    const int kofs    = (TPC > 1) ? (tid / BN) : 0;

    int  col_[CPT];
    bool nok_[CPT];
    int  iy0_[CPT], ix0_[CPT];
    size_t base_[CPT];
    #pragma unroll
    for (int c = 0; c < CPT; c++) {
        int col = colbase + c * THREADS;
        col_[c] = col;
        int gn = n0 + col;
        bool ok = (N % BN == 0) || (gn < N);
        nok_[c] = ok;
        int gsafe = ok ? gn : 0;
        int bb = gsafe / P;
        int pp = gsafe - bb * P;
        int oy = pp / WOUT;
        int ox = pp - oy * WOUT;
        iy0_[c] = 2 * oy;
        ix0_[c] = 2 * ox;
        base_[c] = (NCHW ? (size_t)bb * CIN : (size_t)bb) * HWIN;
    }

    float ar[AE];
    float br[CPT][RPT];

    u64 acc[8][4];
    #pragma unroll
    for (int i = 0; i < 8; i++)
        #pragma unroll
        for (int j = 0; j < 4; j++) acc[i][j] = pack2(0.f, 0.f);

    auto gatherB = [&](int kt) {
        if (REORD) {
            // whole tile shares (ky,kx); channels advance by 1 per k-row
            const int kg0 = k00 + kt;
            const int t   = kg0 / CIN;
            const int ky  = t / 3;
            const int kx  = t - 3 * ky;
            const int c0  = kg0 - t * CIN;
            #pragma unroll
            for (int c = 0; c < CPT; c++) {
                const int iy = iy0_[c] + ky;
                const int ix = ix0_[c] + kx;
                const bool ok = nok_[c] && (iy < HIN) && (ix < WIN);
                const float* bp = act + base_[c] + iy * WIN + ix
                                + (size_t)(c0 + kofs) * CSTR;
                #pragma unroll
                for (int j = 0; j < RPT; j++)
                    br[c][j] = ok ? __ldg(bp + (size_t)(j * TPC) * CSTR) : 0.f;
            }
        } else {
            #pragma unroll
            for (int c = 0; c < CPT; c++) {
                #pragma unroll
                for (int j = 0; j < RPT; j++) {
                    int kl = kt + j * TPC + kofs;
                    int kg = k00 + kl;
                    int ch = kg / 9;
                    int t  = kg - 9 * ch;
                    int ky = t / 3;
                    int kx = t - 3 * ky;
                    int iy = iy0_[c] + ky;
                    int ix = ix0_[c] + kx;
                    bool ok = nok_[c] && (iy < HIN) && (ix < WIN);
                    if (KC % BK != 0) ok = ok && (kl < KC);
                    br[c][j] = ok ? __ldg(act + base_[c] + (size_t)ch * CSTR + iy * WIN + ix) : 0.f;
                }
            }
        }
    };
    auto gatherA = [&](int kt) {
        #pragma unroll
        for (int j = 0; j < AE; j++) {
            int i = tid + j * THREADS;
            int m = i >> 4, kk = i & 15;
            bool ok = true;
            if (M % BM != 0) ok = (m0 + m) < M;
            if (KC % BK != 0) ok = ok && ((kt + kk) < KC);
            ar[j] = ok ? A[(size_t)(m0 + m) * K + k00 + kt + kk] : 0.f;
        }
    };

    gatherB(0);
    gatherA(0);
    #pragma unroll
    for (int c = 0; c < CPT; c++)
        #pragma unroll
        for (int j = 0; j < RPT; j++) Bs[0][j * TPC + kofs][col_[c]] = br[c][j];
    #pragma unroll
    for (int j = 0; j < AE; j++) {
        int i = tid + j * THREADS;
        As[0][i & 15][i >> 4] = ar[j];
    }
    __syncthreads();

    int buf = 0;
    for (int tt = 0; tt < NT_; tt++) {
        const bool has_next = (tt + 1) < NT_;
        if (has_next) {
            gatherB((tt + 1) * BK);
            gatherA((tt + 1) * BK);
        }

        #pragma unroll
        for (int kk = 0; kk < BK; kk++) {
            float4 a0 = *reinterpret_cast<const float4*>(&As[buf][kk][ty * 8]);
            float4 a1 = *reinterpret_cast<const float4*>(&As[buf][kk][ty * 8 + 4]);
            float4 bA = *reinterpret_cast<const float4*>(&Bs[buf][kk][tx * 8]);
            float4 bB = *reinterpret_cast<const float4*>(&Bs[buf][kk][tx * 8 + 4]);
            u64 b01 = pack2(bA.x, bA.y);
            u64 b23 = pack2(bA.z, bA.w);
            u64 b45 = pack2(bB.x, bB.y);
            u64 b67 = pack2(bB.z, bB.w);
            float av[8] = {a0.x, a0.y, a0.z, a0.w, a1.x, a1.y, a1.z, a1.w};
            #pragma unroll
            for (int i = 0; i < 8; i++) {
                u64 ap = pack2(av[i], av[i]);
                acc[i][0] = fma2(ap, b01, acc[i][0]);
                acc[i][1] = fma2(ap, b23, acc[i][1]);
                acc[i][2] = fma2(ap, b45, acc[i][2]);
                acc[i][3] = fma2(ap, b67, acc[i][3]);
            }
        }

        if (has_next) {
            #pragma unroll
            for (int c = 0; c < CPT; c++)
                #pragma unroll
                for (int j = 0; j < RPT; j++) Bs[buf ^ 1][j * TPC + kofs][col_[c]] = br[c][j];
            #pragma unroll
            for (int j = 0; j < AE; j++) {
                int i = tid + j * THREADS;
                As[buf ^ 1][i & 15][i >> 4] = ar[j];
            }
            __syncthreads();
            buf ^= 1;
        }
    }

    float* Cb = (SK == 1) ? C : (C + (size_t)blockIdx.z * M * N);
    #pragma unroll
    for (int i = 0; i < 8; i++) {
        int m = m0 + ty * 8 + i;
        if (M % BM != 0 && m >= M) continue;
        int go = n0 + tx * 8;
        if (N % BN != 0 && go >= N) continue;
        float x0, x1, x2, x3, x4, x5, x6, x7;
        unpack2(acc[i][0], x0, x1);
        unpack2(acc[i][1], x2, x3);
        unpack2(acc[i][2], x4, x5);
        unpack2(acc[i][3], x6, x7);
        if (SK == 1) {
            float bbv = bias[m];
            x0 += bbv; x1 += bbv; x2 += bbv; x3 += bbv;
            x4 += bbv; x5 += bbv; x6 += bbv; x7 += bbv;
            if (LRELU) {
                x0 = x0 > 0.f ? x0 : 0.1f * x0;
                x1 = x1 > 0.f ? x1 : 0.1f * x1;
                x2 = x2 > 0.f ? x2 : 0.1f * x2;
                x3 = x3 > 0.f ? x3 : 0.1f * x3;
                x4 = x4 > 0.f ? x4 : 0.1f * x4;
                x5 = x5 > 0.f ? x5 : 0.1f * x5;
                x6 = x6 > 0.f ? x6 : 0.1f * x6;
                x7 = x7 > 0.f ? x7 : 0.1f * x7;
            }
        }
        *reinterpret_cast<float4*>(&Cb[(size_t)m * N + go])     = make_float4(x0, x1, x2, x3);
        *reinterpret_cast<float4*>(&Cb[(size_t)m * N + go + 4]) = make_float4(x4, x5, x6, x7);
    }
}

// ---------------- plain GEMM (heads): 8x8 tile, cp.async B, double-buffer --
template <int M, int N, int K, int BM, int BN, int SK, int THREADS, bool LRELU>
__global__ void __launch_bounds__(THREADS, (THREADS == 128 ? 4 : 2))
gemm9_kernel(const float* __restrict__ A, const float* __restrict__ B,
             const float* __restrict__ bias, float* __restrict__ C)
{
    constexpr int BK = 16;
    constexpr int TX = BN / 8;
    constexpr int TY = BM / 8;
    static_assert(TX * TY == THREADS, "threads");
    constexpr int KC = K / SK;
    static_assert(KC % BK == 0, "K chunk");
    constexpr int NB4 = BN / 4;
    constexpr int AE  = BM * BK / THREADS;
    constexpr int BE4 = BK * NB4 / THREADS;

    __shared__ __align__(16) float  As[2][BK][BM + 4];
    __shared__ __align__(16) float4 Bs[2][BK][NB4];

    const int tid = threadIdx.x;
    const int tx  = tid % TX;
    const int ty  = tid / TX;
    const int m0  = blockIdx.y * BM;
    const int n0  = blockIdx.x * BN;
    const int k00 = blockIdx.z * KC;

    float ar[AE];

    u64 acc[8][4];
    #pragma unroll
    for (int i = 0; i < 8; i++)
        #pragma unroll
        for (int j = 0; j < 4; j++) acc[i][j] = pack2(0.f, 0.f);

    #pragma unroll
    for (int j = 0; j < BE4; j++) {
        int i = tid + j * THREADS;
        int kk = i / NB4, n4 = i % NB4;
        int gn = n0 + n4 * 4;
        bool ok = (N % BN == 0) || (gn < N);
        const float* src = ok ? &B[(size_t)(k00 + kk) * N + gn] : B;
        cp_async16(smem_u32(&Bs[0][kk][n4]), src, ok);
    }
    cp_commit();
    #pragma unroll
    for (int j = 0; j < AE; j++) {
        int i = tid + j * THREADS;
        int kk = i % BK, m = i / BK;
        float v = 0.f;
        if (M % BM == 0 || (m0 + m) < M) v = A[(size_t)(m0 + m) * K + k00 + kk];
        ar[j] = v;
    }
    #pragma unroll
    for (int j = 0; j < AE; j++) {
        int i = tid + j * THREADS;
        As[0][i % BK][i / BK] = ar[j];
    }
    cp_wait0();
    __syncthreads();

    int buf = 0;
    for (int kt = 0; kt < KC; kt += BK) {
        const bool has_next = (kt + BK) < KC;
        if (has_next) {
            #pragma unroll
            for (int j = 0; j < BE4; j++) {
                int i = tid + j * THREADS;
                int kk = i / NB4, n4 = i % NB4;
                int gn = n0 + n4 * 4;
                bool ok = (N % BN == 0) || (gn < N);
                const float* src = ok ? &B[(size_t)(k00 + kt + BK + kk) * N + gn] : B;
                cp_async16(smem_u32(&Bs[buf ^ 1][kk][n4]), src, ok);
            }
            cp_commit();
            #pragma unroll
            for (int j = 0; j < AE; j++) {
                int i = tid + j * THREADS;
                int kk = i % BK, m = i / BK;
                float v = 0.f;
                if (M % BM == 0 || (m0 + m) < M)
                    v = A[(size_t)(m0 + m) * K + k00 + kt + BK + kk];
                ar[j] = v;
            }
        }

        #pragma unroll
        for (int kk = 0; kk < BK; kk++) {
            float4 a0 = *reinterpret_cast<const float4*>(&As[buf][kk][ty * 8]);
            float4 a1 = *reinterpret_cast<const float4*>(&As[buf][kk][ty * 8 + 4]);
            float4 bA = Bs[buf][kk][tx * 2];
            float4 bB = Bs[buf][kk][tx * 2 + 1];
            u64 b01 = pack2(bA.x, bA.y);
            u64 b23 = pack2(bA.z, bA.w);
            u64 b45 = pack2(bB.x, bB.y);
            u64 b67 = pack2(bB.z, bB.w);
            float av[8] = {a0.x, a0.y, a0.z, a0.w, a1.x, a1.y, a1.z, a1.w};
            #pragma unroll
            for (int i = 0; i < 8; i++) {
                u64 ap = pack2(av[i], av[i]);
                acc[i][0] = fma2(ap, b01, acc[i][0]);
                acc[i][1] = fma2(ap, b23, acc[i][1]);
                acc[i][2] = fma2(ap, b45, acc[i][2]);
                acc[i][3] = fma2(ap, b67, acc[i][3]);
            }
        }

        if (has_next) {
            #pragma unroll
            for (int j = 0; j < AE; j++) {
                int i = tid + j * THREADS;
                As[buf ^ 1][i % BK][i / BK] = ar[j];
            }
            cp_wait0();
            __syncthreads();
            buf ^= 1;
        }
    }

    float* Cb = (SK == 1) ? C : (C + (size_t)blockIdx.z * M * N);
    #pragma unroll
    for (int i = 0; i < 8; i++) {
        int m = m0 + ty * 8 + i;
        if (M % BM != 0 && m >= M) continue;
        int gn = n0 + tx * 8;
        if (N % BN != 0 && gn >= N) continue;
        float x0, x1, x2, x3, x4, x5, x6, x7;
        unpack2(acc[i][0], x0, x1);
        unpack2(acc[i][1], x2, x3);
        unpack2(acc[i][2], x4, x5);
        unpack2(acc[i][3], x6, x7);
        if (SK == 1) {
            float bb = bias[m];
            x0 += bb; x1 += bb; x2 += bb; x3 += bb;
            x4 += bb; x5 += bb; x6 += bb; x7 += bb;
            if (LRELU) {
                x0 = x0 > 0.f ? x0 : 0.1f * x0;
                x1 = x1 > 0.f ? x1 : 0.1f * x1;
                x2 = x2 > 0.f ? x2 : 0.1f * x2;
                x3 = x3 > 0.f ? x3 : 0.1f * x3;
                x4 = x4 > 0.f ? x4 : 0.1f * x4;
                x5 = x5 > 0.f ? x5 : 0.1f * x5;
                x6 = x6 > 0.f ? x6 : 0.1f * x6;
                x7 = x7 > 0.f ? x7 : 0.1f * x7;
            }
        }
        *reinterpret_cast<float4*>(&Cb[(size_t)m * N + gn])     = make_float4(x0, x1, x2, x3);
        *reinterpret_cast<float4*>(&Cb[(size_t)m * N + gn + 4]) = make_float4(x4, x5, x6, x7);
    }
}

// ---------------- split-K reduce: C = sum_sk part + bias (+lrelu) ----------
template <int M, int N, int SK, bool LRELU>
__global__ void reduce_kernel(const float* __restrict__ part,
                              const float* __restrict__ bias,
                              float* __restrict__ C)
{
    int i4 = (blockIdx.x * 256 + threadIdx.x) * 4;
    if (i4 >= M * N) return;
    float4 s = *reinterpret_cast<const float4*>(&part[i4]);
    #pragma unroll
    for (int sk = 1; sk < SK; sk++) {
        float4 p = *reinterpret_cast<const float4*>(&part[(size_t)sk * M * N + i4]);
        s.x += p.x; s.y += p.y; s.z += p.z; s.w += p.w;
    }
    float bb = bias[i4 / N];
    s.x += bb; s.y += bb; s.z += bb; s.w += bb;
    if (LRELU) {
        s.x = s.x > 0.f ? s.x : 0.1f * s.x;
        s.y = s.y > 0.f ? s.y : 0.1f * s.y;
        s.z = s.z > 0.f ? s.z : 0.1f * s.z;
        s.w = s.w > 0.f ? s.w : 0.1f * s.w;
    }
    *reinterpret_cast<float4*>(&C[i4]) = s;
}

// ---------------- decode: feat (CNHW) -> candidate record ----------------
__device__ __forceinline__ float sigmoidf_(float x) { return 1.f / (1.f + expf(-x)); }

__global__ void decode_kernel(const float* __restrict__ feat1,
                              const float* __restrict__ feat2,
                              float* __restrict__ cand)
{
    int idx = blockIdx.x * blockDim.x + threadIdx.x;
    if (idx >= BATCH * NCAND) return;
    int b = idx / NCAND;
    int n = idx - b * NCAND;

    const float A1w[3] = {81.f, 135.f, 344.f}, A1h[3] = {82.f, 169.f, 319.f};
    const float A2w[3] = {10.f, 23.f,  37.f},  A2h[3] = {14.f, 27.f,  58.f};

    const float* base;
    int H, W, a, yy, xx;
    size_t estr;
    float aw, ah;
    if (n < 507) {
        H = 13; W = 13;
        a = n / 169; int r = n - a * 169; yy = r / 13; xx = r - yy * 13;
        aw = A1w[a]; ah = A1h[a];
        estr = (size_t)BATCH * 169;
        base = feat1 + (size_t)(a * 85) * estr + b * 169 + yy * 13 + xx;
    } else {
        int m = n - 507;
        H = 26; W = 26;
        a = m / 676; int r = m - a * 676; yy = r / 26; xx = r - yy * 26;
        aw = A2w[a]; ah = A2h[a];
        estr = (size_t)BATCH * 676;
        base = feat2 + (size_t)(a * 85) * estr + b * 676 + yy * 26 + xx;
    }

    float t0 = base[0];
    float t1 = base[estr];
    float t2 = base[2 * estr];
    float t3 = base[3 * estr];
    float t4 = base[4 * estr];

    float bx = (sigmoidf_(t0) + (float)xx) / (float)W;
    float by = (sigmoidf_(t1) + (float)yy) / (float)H;
    float bw = expf(t2) * aw / 416.f;
    float bh = expf(t3) * ah / 416.f;
    float obj = sigmoidf_(t4);

    float ml = base[5 * estr];
    int lab = 0;
    for (int c = 1; c < 80; c++) {
        float v = base[(5 + c) * estr];
        if (v > ml) { ml = v; lab = c; }
    }
    float cc = sigmoidf_(ml);
    float score = obj * cc;
    if (!(score >= 0.1f)) score = 0.f;

    float* o = cand + (size_t)idx * 8;
    o[0] = (by - bh * 0.5f) * 416.f;
    o[1] = (bx - bw * 0.5f) * 416.f;
    o[2] = (by + bh * 0.5f) * 416.f;
    o[3] = (bx + bw * 0.5f) * 416.f;
    o[4] = obj;
    o[5] = cc;
    o[6] = (float)lab;
    o[7] = score;
}

// ---------------- per-image top-k (bitonic) + greedy NMS ----------------
__global__ void nms_kernel(const float* __restrict__ cand, float* __restrict__ out)
{
    const int b = blockIdx.x;
    const int tid = threadIdx.x; // 1024 threads

    __shared__ u64 keys[NPAD];

    const float* cb = cand + (size_t)b * NCAND * 8;

    for (int i = tid; i < NPAD; i += 1024) {
        u64 k = 0;
        if (i < NCAND) {
            float sc = cb[i * 8 + 7];
            k = ((u64)__float_as_uint(sc) << 32) | (u64)(0xFFFFFFFFu - (unsigned)i);
        }
        keys[i] = k;
    }
    __syncthreads();

    for (int k = 2; k <= NPAD; k <<= 1) {
        for (int j = k >> 1; j > 0; j >>= 1) {
            #pragma unroll 2
            for (int t = tid; t < NPAD / 2; t += 1024) {
                int i = ((t / j) * (j << 1)) + (t % j);
                int l = i + j;
                u64 a = keys[i], c = keys[l];
                bool desc = ((i & k) == 0);
                if (desc ? (a < c) : (a > c)) { keys[i] = c; keys[l] = a; }
            }
            __syncthreads();
        }
    }

    __shared__ float y0s[TOPK], x0s[TOPK], y1s[TOPK], x1s[TOPK], areas[TOPK];
    __shared__ int labs[TOPK];
    __shared__ int sel[TOPK];
    __shared__ unsigned char keep[TOPK];
    if (tid < TOPK) {
        u64 k = keys[tid];
        int ii = (int)(0xFFFFFFFFu - (unsigned)(k & 0xFFFFFFFFu));
        sel[tid] = ii;
        float y0 = cb[ii * 8 + 0], x0 = cb[ii * 8 + 1];
        float y1 = cb[ii * 8 + 2], x1 = cb[ii * 8 + 3];
        y0s[tid] = y0; x0s[tid] = x0; y1s[tid] = y1; x1s[tid] = x1;
        areas[tid] = (y1 - y0) * (x1 - x0);
        labs[tid] = (int)cb[ii * 8 + 6];
        keep[tid] = ((unsigned)(k >> 32) != 0u) ? 1 : 0;
    }
    __syncthreads();

    for (int j = 0; j < TOPK - 1; j++) {
        if (tid > j && tid < TOPK && keep[j] && keep[tid] && labs[tid] == labs[j]) {
            float ty0 = fmaxf(y0s[tid], y0s[j]);
            float tx0 = fmaxf(x0s[tid], x0s[j]);
            float ty1 = fminf(y1s[tid], y1s[j]);
            float tx1 = fminf(x1s[tid], x1s[j]);
            float ih = fmaxf(ty1 - ty0, 0.f);
            float iw = fmaxf(tx1 - tx0, 0.f);
            float inter = ih * iw;
            float iou = inter / (areas[tid] + areas[j] - inter + 1e-9f);
            if (iou > 0.5f) keep[tid] = 0;
        }
        __syncthreads();
    }

    if (tid < TOPK) {
        float* o = out + ((size_t)b * TOPK + tid) * 7;
        if (keep[tid]) {
            int ii = sel[tid];
            o[0] = y0s[tid]; o[1] = x0s[tid]; o[2] = y1s[tid]; o[3] = x1s[tid];
            o[4] = cb[ii * 8 + 4];
            o[5] = cb[ii * 8 + 5];
            o[6] = (float)labs[tid];
        } else {
            #pragma unroll
            for (int k = 0; k < 7; k++) o[k] = 0.f;
        }
    }
}

// ---------------- launch ----------------
static inline int ceil_div(int a, int b) { return (a + b - 1) / b; }

extern "C" void kernel_launch(void* const* d_in, const int* in_sizes, int n_in,
                              void* d_out, int out_size)
{
    (void)in_sizes; (void)n_in; (void)out_size;
    const float* images = (const float*)d_in[0];
    const float* w1 = (const float*)d_in[1];  const float* b1 = (const float*)d_in[2];
    const float* w2 = (const float*)d_in[3];  const float* b2 = (const float*)d_in[4];
    const float* w3 = (const float*)d_in[5];  const float* b3 = (const float*)d_in[6];
    const float* w4 = (const float*)d_in[7];  const float* b4 = (const float*)d_in[8];
    const float* w5 = (const float*)d_in[9];  const float* b5 = (const float*)d_in[10];
    const float* wh1 = (const float*)d_in[11]; const float* bh1 = (const float*)d_in[12];
    const float* wh2 = (const float*)d_in[13]; const float* bh2 = (const float*)d_in[14];
    float* out = (float*)d_out;

    static float *act1 = nullptr, *act2, *act3, *act4, *act5, *feat1, *feat2, *part, *cand, *wperm;
    if (!act1) {
        cudaGetSymbolAddress((void**)&act1, g_act1);
        cudaGetSymbolAddress((void**)&act2, g_act2);
        cudaGetSymbolAddress((void**)&act3, g_act3);
        cudaGetSymbolAddress((void**)&act4, g_act4);
        cudaGetSymbolAddress((void**)&act5, g_act5);
        cudaGetSymbolAddress((void**)&feat1, g_feat1);
        cudaGetSymbolAddress((void**)&feat2, g_feat2);
        cudaGetSymbolAddress((void**)&part, g_part);
        cudaGetSymbolAddress((void**)&cand, g_cand);
        cudaGetSymbolAddress((void**)&wperm, g_wperm);
    }

    // --- fused weight k-reorder (single launch, all 4 layers)
    const int O2 = 0, O3 = 18432, O4 = 92160, O5 = 387072;
    wperm_all_kernel<<<ceil_div(1566720, 256), 256>>>(w2, w3, w4, w5, wperm);

    // --- L1: 3->32, 416->208  (N = 346112, K = 27), BM=32, 64 thr (no reorder)
    gemm9f_kernel<32, 346112, 27, 32, 1, true, true, false, 3, 416, 416, 208, 208, 64>
        <<<dim3(346112 / 128, 1, 1), 64>>>(w1, images, b1, act1);

    // --- L2: 32->64, 208->104 (N = 86528, K = 288), BM=64, reordered
    gemm9f_kernel<64, 86528, 288, 64, 1, true, false, true, 32, 208, 208, 104, 104, 128>
        <<<dim3(86528 / 128, 1, 1), 128>>>(wperm + O2, act1, b2, act2);

    // --- L3: 64->128, 104->52 (N = 21632, K = 576), BM=64, reordered
    gemm9f_kernel<128, 21632, 576, 64, 1, true, false, true, 64, 104, 104, 52, 52, 128>
        <<<dim3(21632 / 128, 2, 1), 128>>>(wperm + O3, act2, b3, act3);

    // --- L4: 128->256, 52->26 (N = 5408, K = 1152), BM=64, split-K 4, reordered
    gemm9f_kernel<256, 5408, 1152, 64, 4, false, false, true, 128, 52, 52, 26, 26, 128>
        <<<dim3(ceil_div(5408, 128), 4, 4), 128>>>(wperm + O4, act3, b4, part);
    reduce_kernel<256, 5408, 4, true>
        <<<ceil_div(256 * 5408 / 4, 256), 256>>>(part, b4, act4);

    // --- head2: 255 x 5408, K = 256, split-K 2
    gemm9_kernel<255, 5408, 256, 128, 128, 2, 256, false>
        <<<dim3(ceil_div(5408, 128), 2, 2), 256>>>(wh2, act4, bh2, part);
    reduce_kernel<255, 5408, 2, false>
        <<<ceil_div(255 * 5408 / 4 + 1, 256), 256>>>(part, bh2, feat2);

    // --- L5: 256->512, 26->13 (N = 1352, K = 2304), BM=64, split-K 4, reordered
    gemm9f_kernel<512, 1352, 2304, 64, 4, false, false, true, 256, 26, 26, 13, 13, 128>
        <<<dim3(ceil_div(1352, 128), 8, 4), 128>>>(wperm + O5, act4, b5, part);
    reduce_kernel<512, 1352, 4, true>
        <<<ceil_div(512 * 1352 / 4, 256), 256>>>(part, b5, act5);

    // --- head1: 255 x 1352, K = 512, split-K 4
    gemm9_kernel<255, 1352, 512, 128, 128, 4, 256, false>
        <<<dim3(ceil_div(1352, 128), 2, 4), 256>>>(wh1, act5, bh1, part);
    reduce_kernel<255, 1352, 4, false>
        <<<ceil_div(255 * 1352 / 4 + 1, 256), 256>>>(part, bh1, feat1);

    // --- decode + nms
    decode_kernel<<<ceil_div(BATCH * NCAND, 256), 256>>>(feat1, feat2, cand);
    nms_kernel<<<BATCH, 1024>>>(cand, out);
}

// round 17
// speedup vs baseline: 1.0893x; 1.0365x over previous
#include <cuda_runtime.h>
#include <cstdint>

#define BATCH 8
#define NCAND 2535   // 3*13*13 + 3*26*26
#define TOPK 300
#define NPAD 4096

typedef unsigned long long u64;

__device__ __forceinline__ u64 pack2(float x, float y) {
    u64 r;
    asm("mov.b64 %0, {%1, %2};" : "=l"(r)
        : "r"(__float_as_uint(x)), "r"(__float_as_uint(y)));
    return r;
}
__device__ __forceinline__ void unpack2(u64 v, float& x, float& y) {
    unsigned a, b;
    asm("mov.b64 {%0, %1}, %2;" : "=r"(a), "=r"(b) : "l"(v));
    x = __uint_as_float(a); y = __uint_as_float(b);
}
__device__ __forceinline__ u64 fma2(u64 a, u64 b, u64 c) {
    u64 d;
    asm("fma.rn.f32x2 %0, %1, %2, %3;" : "=l"(d) : "l"(a), "l"(b), "l"(c));
    return d;
}
__device__ __forceinline__ unsigned smem_u32(const void* p) {
    return (unsigned)__cvta_generic_to_shared(p);
}
__device__ __forceinline__ void cp_async16(unsigned dst, const void* src, bool valid) {
    int sz = valid ? 16 : 0;
    asm volatile("cp.async.ca.shared.global [%0], [%1], 16, %2;\n"
                 :: "r"(dst), "l"(src), "r"(sz) : "memory");
}
__device__ __forceinline__ void cp_commit() {
    asm volatile("cp.async.commit_group;\n" ::: "memory");
}
__device__ __forceinline__ void cp_wait0() {
    asm volatile("cp.async.wait_group 0;\n" ::: "memory");
}

// ---------------- scratch (device globals; no allocation) ----------------
__device__ float g_act1[32  * BATCH * 208 * 208];
__device__ float g_act2[64  * BATCH * 104 * 104];
__device__ float g_act3[128 * BATCH * 52  * 52];
__device__ float g_act4[256 * BATCH * 26  * 26];
__device__ float g_act5[512 * BATCH * 13  * 13];
__device__ float g_feat1[255 * BATCH * 13 * 13];
__device__ float g_feat2[255 * BATCH * 26 * 26];
__device__ float g_part[8 * 512 * 5408];          // split-K partials
__device__ float g_cand[BATCH * NCAND * 8];
__device__ float g_wperm[1566720];                // k-reordered weights L2..L5
// offsets (elements): L2:0  L3:18432  L4:92160  L5:387072

// ---------------- fused weight permute for all 4 layers ------------------
__global__ void wperm_all_kernel(const float* __restrict__ w2,
                                 const float* __restrict__ w3,
                                 const float* __restrict__ w4,
                                 const float* __restrict__ w5,
                                 float* __restrict__ wp)
{
    int i = blockIdx.x * 256 + threadIdx.x;
    const float* w;
    int CIN, base;
    if (i < 18432)        { w = w2; CIN = 32;  base = 0; }
    else if (i < 92160)   { w = w3; CIN = 64;  base = 18432; }
    else if (i < 387072)  { w = w4; CIN = 128; base = 92160; }
    else if (i < 1566720) { w = w5; CIN = 256; base = 387072; }
    else return;
    int li = i - base;
    int K = CIN * 9;
    int m = li / K;
    int k = li - m * K;
    int t = k / CIN;
    int c = k - t * CIN;
    wp[i] = w[(size_t)m * K + c * 9 + t];
}

// ---------------- fused im2col GEMM: 3x3 stride-2 conv as implicit GEMM ----
template <int M, int N, int K, int BM, int SK, bool LRELU, bool NCHW, bool REORD,
          int CIN, int HIN, int WIN, int HOUT, int WOUT, int THREADS>
__global__ void __launch_bounds__(THREADS, (THREADS == 128 ? 3 : (THREADS == 64 ? 6 : 2)))
gemm9f_kernel(const float* __restrict__ A, const float* __restrict__ act,
              const float* __restrict__ bias, float* __restrict__ C)
{
    constexpr int BN = 128, BK = 16;
    constexpr int TX = BN / 8;
    constexpr int TY = BM / 8;
    static_assert(TX * TY == THREADS, "threads");
    constexpr int CPT = (THREADS < BN) ? (BN / THREADS) : 1;
    constexpr int TPC = (THREADS < BN) ? 1 : (THREADS / BN);
    constexpr int RPT = BK / TPC;
    constexpr int KC = (K % SK == 0) ? (K / SK) : K;
    constexpr int NT_ = (KC + BK - 1) / BK;
    constexpr int P = HOUT * WOUT;
    constexpr int HWIN = HIN * WIN;
    constexpr int AE = BM * BK / THREADS;
    constexpr size_t CSTR = NCHW ? (size_t)HWIN : (size_t)BATCH * HWIN;
    static_assert(!REORD || (CIN % BK == 0 && KC % BK == 0), "reorder alignment");

    __shared__ __align__(16) float As[2][BK][BM + 4];
    __shared__ __align__(16) float Bs[2][BK][BN];

    const int tid = threadIdx.x;
    const int tx  = tid % TX;
    const int ty  = tid / TX;
    const int m0  = blockIdx.y * BM;
    const int n0  = blockIdx.x * BN;
    const int k00 = blockIdx.z * KC;

    const int colbase = (CPT > 1) ? tid : (tid % BN);
    const int kofs    = (TPC > 1) ? (tid / BN) : 0;

    int  col_[CPT];
    bool nok_[CPT];
    int  iy0_[CPT], ix0_[CPT];
    size_t base_[CPT];
    #pragma unroll
    for (int c = 0; c < CPT; c++) {
        int col = colbase + c * THREADS;
        col_[c] = col;
        int gn = n0 + col;
        bool ok = (N % BN == 0) || (gn < N);
        nok_[c] = ok;
        int gsafe = ok ? gn : 0;
        int bb = gsafe / P;
        int pp = gsafe - bb * P;
        int oy = pp / WOUT;
        int ox = pp - oy * WOUT;
        iy0_[c] = 2 * oy;
        ix0_[c] = 2 * ox;
        base_[c] = (NCHW ? (size_t)bb * CIN : (size_t)bb) * HWIN;
    }

    float ar[AE];
    float br[CPT][RPT];

    u64 acc[8][4];
    #pragma unroll
    for (int i = 0; i < 8; i++)
        #pragma unroll
        for (int j = 0; j < 4; j++) acc[i][j] = pack2(0.f, 0.f);

    auto gatherB = [&](int kt) {
        if (REORD) {
            const int kg0 = k00 + kt;
            const int t   = kg0 / CIN;
            const int ky  = t / 3;
            const int kx  = t - 3 * ky;
            const int c0  = kg0 - t * CIN;
            #pragma unroll
            for (int c = 0; c < CPT; c++) {
                const int iy = iy0_[c] + ky;
                const int ix = ix0_[c] + kx;
                const bool ok = nok_[c] && (iy < HIN) && (ix < WIN);
                const float* bp = act + base_[c] + iy * WIN + ix
                                + (size_t)(c0 + kofs) * CSTR;
                #pragma unroll
                for (int j = 0; j < RPT; j++)
                    br[c][j] = ok ? __ldg(bp + (size_t)(j * TPC) * CSTR) : 0.f;
            }
        } else {
            #pragma unroll
            for (int c = 0; c < CPT; c++) {
                #pragma unroll
                for (int j = 0; j < RPT; j++) {
                    int kl = kt + j * TPC + kofs;
                    int kg = k00 + kl;
                    int ch = kg / 9;
                    int t  = kg - 9 * ch;
                    int ky = t / 3;
                    int kx = t - 3 * ky;
                    int iy = iy0_[c] + ky;
                    int ix = ix0_[c] + kx;
                    bool ok = nok_[c] && (iy < HIN) && (ix < WIN);
                    if (KC % BK != 0) ok = ok && (kl < KC);
                    br[c][j] = ok ? __ldg(act + base_[c] + (size_t)ch * CSTR + iy * WIN + ix) : 0.f;
                }
            }
        }
    };
    auto gatherA = [&](int kt) {
        #pragma unroll
        for (int j = 0; j < AE; j++) {
            int i = tid + j * THREADS;
            int m = i >> 4, kk = i & 15;
            bool ok = true;
            if (M % BM != 0) ok = (m0 + m) < M;
            if (KC % BK != 0) ok = ok && ((kt + kk) < KC);
            ar[j] = ok ? A[(size_t)(m0 + m) * K + k00 + kt + kk] : 0.f;
        }
    };

    gatherB(0);
    gatherA(0);
    #pragma unroll
    for (int c = 0; c < CPT; c++)
        #pragma unroll
        for (int j = 0; j < RPT; j++) Bs[0][j * TPC + kofs][col_[c]] = br[c][j];
    #pragma unroll
    for (int j = 0; j < AE; j++) {
        int i = tid + j * THREADS;
        As[0][i & 15][i >> 4] = ar[j];
    }
    __syncthreads();

    int buf = 0;
    for (int tt = 0; tt < NT_; tt++) {
        const bool has_next = (tt + 1) < NT_;
        if (has_next) {
            gatherB((tt + 1) * BK);
            gatherA((tt + 1) * BK);
        }

        #pragma unroll
        for (int kk = 0; kk < BK; kk++) {
            float4 a0 = *reinterpret_cast<const float4*>(&As[buf][kk][ty * 8]);
            float4 a1 = *reinterpret_cast<const float4*>(&As[buf][kk][ty * 8 + 4]);
            float4 bA = *reinterpret_cast<const float4*>(&Bs[buf][kk][tx * 8]);
            float4 bB = *reinterpret_cast<const float4*>(&Bs[buf][kk][tx * 8 + 4]);
            u64 b01 = pack2(bA.x, bA.y);
            u64 b23 = pack2(bA.z, bA.w);
            u64 b45 = pack2(bB.x, bB.y);
            u64 b67 = pack2(bB.z, bB.w);
            float av[8] = {a0.x, a0.y, a0.z, a0.w, a1.x, a1.y, a1.z, a1.w};
            #pragma unroll
            for (int i = 0; i < 8; i++) {
                u64 ap = pack2(av[i], av[i]);
                acc[i][0] = fma2(ap, b01, acc[i][0]);
                acc[i][1] = fma2(ap, b23, acc[i][1]);
                acc[i][2] = fma2(ap, b45, acc[i][2]);
                acc[i][3] = fma2(ap, b67, acc[i][3]);
            }
        }

        if (has_next) {
            #pragma unroll
            for (int c = 0; c < CPT; c++)
                #pragma unroll
                for (int j = 0; j < RPT; j++) Bs[buf ^ 1][j * TPC + kofs][col_[c]] = br[c][j];
            #pragma unroll
            for (int j = 0; j < AE; j++) {
                int i = tid + j * THREADS;
                As[buf ^ 1][i & 15][i >> 4] = ar[j];
            }
            __syncthreads();
            buf ^= 1;
        }
    }

    float* Cb = (SK == 1) ? C : (C + (size_t)blockIdx.z * M * N);
    #pragma unroll
    for (int i = 0; i < 8; i++) {
        int m = m0 + ty * 8 + i;
        if (M % BM != 0 && m >= M) continue;
        int go = n0 + tx * 8;
        if (N % BN != 0 && go >= N) continue;
        float x0, x1, x2, x3, x4, x5, x6, x7;
        unpack2(acc[i][0], x0, x1);
        unpack2(acc[i][1], x2, x3);
        unpack2(acc[i][2], x4, x5);
        unpack2(acc[i][3], x6, x7);
        if (SK == 1) {
            float bbv = bias[m];
            x0 += bbv; x1 += bbv; x2 += bbv; x3 += bbv;
            x4 += bbv; x5 += bbv; x6 += bbv; x7 += bbv;
            if (LRELU) {
                x0 = x0 > 0.f ? x0 : 0.1f * x0;
                x1 = x1 > 0.f ? x1 : 0.1f * x1;
                x2 = x2 > 0.f ? x2 : 0.1f * x2;
                x3 = x3 > 0.f ? x3 : 0.1f * x3;
                x4 = x4 > 0.f ? x4 : 0.1f * x4;
                x5 = x5 > 0.f ? x5 : 0.1f * x5;
                x6 = x6 > 0.f ? x6 : 0.1f * x6;
                x7 = x7 > 0.f ? x7 : 0.1f * x7;
            }
        }
        *reinterpret_cast<float4*>(&Cb[(size_t)m * N + go])     = make_float4(x0, x1, x2, x3);
        *reinterpret_cast<float4*>(&Cb[(size_t)m * N + go + 4]) = make_float4(x4, x5, x6, x7);
    }
}

// ---------------- plain GEMM (heads): 8x8 tile, cp.async B, double-buffer --
template <int M, int N, int K, int BM, int BN, int SK, int THREADS, bool LRELU>
__global__ void __launch_bounds__(THREADS, (THREADS == 128 ? 4 : 2))
gemm9_kernel(const float* __restrict__ A, const float* __restrict__ B,
             const float* __restrict__ bias, float* __restrict__ C)
{
    constexpr int BK = 16;
    constexpr int TX = BN / 8;
    constexpr int TY = BM / 8;
    static_assert(TX * TY == THREADS, "threads");
    constexpr int KC = K / SK;
    static_assert(KC % BK == 0, "K chunk");
    constexpr int NB4 = BN / 4;
    constexpr int AE  = BM * BK / THREADS;
    constexpr int BE4 = BK * NB4 / THREADS;

    __shared__ __align__(16) float  As[2][BK][BM + 4];
    __shared__ __align__(16) float4 Bs[2][BK][NB4];

    const int tid = threadIdx.x;
    const int tx  = tid % TX;
    const int ty  = tid / TX;
    const int m0  = blockIdx.y * BM;
    const int n0  = blockIdx.x * BN;
    const int k00 = blockIdx.z * KC;

    float ar[AE];

    u64 acc[8][4];
    #pragma unroll
    for (int i = 0; i < 8; i++)
        #pragma unroll
        for (int j = 0; j < 4; j++) acc[i][j] = pack2(0.f, 0.f);

    #pragma unroll
    for (int j = 0; j < BE4; j++) {
        int i = tid + j * THREADS;
        int kk = i / NB4, n4 = i % NB4;
        int gn = n0 + n4 * 4;
        bool ok = (N % BN == 0) || (gn < N);
        const float* src = ok ? &B[(size_t)(k00 + kk) * N + gn] : B;
        cp_async16(smem_u32(&Bs[0][kk][n4]), src, ok);
    }
    cp_commit();
    #pragma unroll
    for (int j = 0; j < AE; j++) {
        int i = tid + j * THREADS;
        int kk = i % BK, m = i / BK;
        float v = 0.f;
        if (M % BM == 0 || (m0 + m) < M) v = A[(size_t)(m0 + m) * K + k00 + kk];
        ar[j] = v;
    }
    #pragma unroll
    for (int j = 0; j < AE; j++) {
        int i = tid + j * THREADS;
        As[0][i % BK][i / BK] = ar[j];
    }
    cp_wait0();
    __syncthreads();

    int buf = 0;
    for (int kt = 0; kt < KC; kt += BK) {
        const bool has_next = (kt + BK) < KC;
        if (has_next) {
            #pragma unroll
            for (int j = 0; j < BE4; j++) {
                int i = tid + j * THREADS;
                int kk = i / NB4, n4 = i % NB4;
                int gn = n0 + n4 * 4;
                bool ok = (N % BN == 0) || (gn < N);
                const float* src = ok ? &B[(size_t)(k00 + kt + BK + kk) * N + gn] : B;
                cp_async16(smem_u32(&Bs[buf ^ 1][kk][n4]), src, ok);
            }
            cp_commit();
            #pragma unroll
            for (int j = 0; j < AE; j++) {
                int i = tid + j * THREADS;
                int kk = i % BK, m = i / BK;
                float v = 0.f;
                if (M % BM == 0 || (m0 + m) < M)
                    v = A[(size_t)(m0 + m) * K + k00 + kt + BK + kk];
                ar[j] = v;
            }
        }

        #pragma unroll
        for (int kk = 0; kk < BK; kk++) {
            float4 a0 = *reinterpret_cast<const float4*>(&As[buf][kk][ty * 8]);
            float4 a1 = *reinterpret_cast<const float4*>(&As[buf][kk][ty * 8 + 4]);
            float4 bA = Bs[buf][kk][tx * 2];
            float4 bB = Bs[buf][kk][tx * 2 + 1];
            u64 b01 = pack2(bA.x, bA.y);
            u64 b23 = pack2(bA.z, bA.w);
            u64 b45 = pack2(bB.x, bB.y);
            u64 b67 = pack2(bB.z, bB.w);
            float av[8] = {a0.x, a0.y, a0.z, a0.w, a1.x, a1.y, a1.z, a1.w};
            #pragma unroll
            for (int i = 0; i < 8; i++) {
                u64 ap = pack2(av[i], av[i]);
                acc[i][0] = fma2(ap, b01, acc[i][0]);
                acc[i][1] = fma2(ap, b23, acc[i][1]);
                acc[i][2] = fma2(ap, b45, acc[i][2]);
                acc[i][3] = fma2(ap, b67, acc[i][3]);
            }
        }

        if (has_next) {
            #pragma unroll
            for (int j = 0; j < AE; j++) {
                int i = tid + j * THREADS;
                As[buf ^ 1][i % BK][i / BK] = ar[j];
            }
            cp_wait0();
            __syncthreads();
            buf ^= 1;
        }
    }

    float* Cb = (SK == 1) ? C : (C + (size_t)blockIdx.z * M * N);
    #pragma unroll
    for (int i = 0; i < 8; i++) {
        int m = m0 + ty * 8 + i;
        if (M % BM != 0 && m >= M) continue;
        int gn = n0 + tx * 8;
        if (N % BN != 0 && gn >= N) continue;
        float x0, x1, x2, x3, x4, x5, x6, x7;
        unpack2(acc[i][0], x0, x1);
        unpack2(acc[i][1], x2, x3);
        unpack2(acc[i][2], x4, x5);
        unpack2(acc[i][3], x6, x7);
        if (SK == 1) {
            float bb = bias[m];
            x0 += bb; x1 += bb; x2 += bb; x3 += bb;
            x4 += bb; x5 += bb; x6 += bb; x7 += bb;
            if (LRELU) {
                x0 = x0 > 0.f ? x0 : 0.1f * x0;
                x1 = x1 > 0.f ? x1 : 0.1f * x1;
                x2 = x2 > 0.f ? x2 : 0.1f * x2;
                x3 = x3 > 0.f ? x3 : 0.1f * x3;
                x4 = x4 > 0.f ? x4 : 0.1f * x4;
                x5 = x5 > 0.f ? x5 : 0.1f * x5;
                x6 = x6 > 0.f ? x6 : 0.1f * x6;
                x7 = x7 > 0.f ? x7 : 0.1f * x7;
            }
        }
        *reinterpret_cast<float4*>(&Cb[(size_t)m * N + gn])     = make_float4(x0, x1, x2, x3);
        *reinterpret_cast<float4*>(&Cb[(size_t)m * N + gn + 4]) = make_float4(x4, x5, x6, x7);
    }
}

// ---------------- split-K reduce: C = sum_sk part + bias (+lrelu) ----------
template <int M, int N, int SK, bool LRELU>
__global__ void reduce_kernel(const float* __restrict__ part,
                              const float* __restrict__ bias,
                              float* __restrict__ C)
{
    int i4 = (blockIdx.x * 256 + threadIdx.x) * 4;
    if (i4 >= M * N) return;
    float4 s = *reinterpret_cast<const float4*>(&part[i4]);
    #pragma unroll
    for (int sk = 1; sk < SK; sk++) {
        float4 p = *reinterpret_cast<const float4*>(&part[(size_t)sk * M * N + i4]);
        s.x += p.x; s.y += p.y; s.z += p.z; s.w += p.w;
    }
    float bb = bias[i4 / N];
    s.x += bb; s.y += bb; s.z += bb; s.w += bb;
    if (LRELU) {
        s.x = s.x > 0.f ? s.x : 0.1f * s.x;
        s.y = s.y > 0.f ? s.y : 0.1f * s.y;
        s.z = s.z > 0.f ? s.z : 0.1f * s.z;
        s.w = s.w > 0.f ? s.w : 0.1f * s.w;
    }
    *reinterpret_cast<float4*>(&C[i4]) = s;
}

// ---------------- decode: feat (CNHW) -> candidate record ----------------
__device__ __forceinline__ float sigmoidf_(float x) { return 1.f / (1.f + expf(-x)); }

__global__ void decode_kernel(const float* __restrict__ feat1,
                              const float* __restrict__ feat2,
                              float* __restrict__ cand)
{
    int idx = blockIdx.x * blockDim.x + threadIdx.x;
    if (idx >= BATCH * NCAND) return;
    int b = idx / NCAND;
    int n = idx - b * NCAND;

    const float A1w[3] = {81.f, 135.f, 344.f}, A1h[3] = {82.f, 169.f, 319.f};
    const float A2w[3] = {10.f, 23.f,  37.f},  A2h[3] = {14.f, 27.f,  58.f};

    const float* base;
    int H, W, a, yy, xx;
    size_t estr;
    float aw, ah;
    if (n < 507) {
        H = 13; W = 13;
        a = n / 169; int r = n - a * 169; yy = r / 13; xx = r - yy * 13;
        aw = A1w[a]; ah = A1h[a];
        estr = (size_t)BATCH * 169;
        base = feat1 + (size_t)(a * 85) * estr + b * 169 + yy * 13 + xx;
    } else {
        int m = n - 507;
        H = 26; W = 26;
        a = m / 676; int r = m - a * 676; yy = r / 26; xx = r - yy * 26;
        aw = A2w[a]; ah = A2h[a];
        estr = (size_t)BATCH * 676;
        base = feat2 + (size_t)(a * 85) * estr + b * 676 + yy * 26 + xx;
    }

    float t0 = base[0];
    float t1 = base[estr];
    float t2 = base[2 * estr];
    float t3 = base[3 * estr];
    float t4 = base[4 * estr];

    float bx = (sigmoidf_(t0) + (float)xx) / (float)W;
    float by = (sigmoidf_(t1) + (float)yy) / (float)H;
    float bw = expf(t2) * aw / 416.f;
    float bh = expf(t3) * ah / 416.f;
    float obj = sigmoidf_(t4);

    float ml = base[5 * estr];
    int lab = 0;
    for (int c = 1; c < 80; c++) {
        float v = base[(5 + c) * estr];
        if (v > ml) { ml = v; lab = c; }
    }
    float cc = sigmoidf_(ml);
    float score = obj * cc;
    if (!(score >= 0.1f)) score = 0.f;

    float* o = cand + (size_t)idx * 8;
    o[0] = (by - bh * 0.5f) * 416.f;
    o[1] = (bx - bw * 0.5f) * 416.f;
    o[2] = (by + bh * 0.5f) * 416.f;
    o[3] = (bx + bw * 0.5f) * 416.f;
    o[4] = obj;
    o[5] = cc;
    o[6] = (float)lab;
    o[7] = score;
}

// ---------------- per-image top-k (bitonic) + greedy NMS ----------------
__global__ void nms_kernel(const float* __restrict__ cand, float* __restrict__ out)
{
    const int b = blockIdx.x;
    const int tid = threadIdx.x; // 1024 threads

    __shared__ u64 keys[NPAD];

    const float* cb = cand + (size_t)b * NCAND * 8;

    for (int i = tid; i < NPAD; i += 1024) {
        u64 k = 0;
        if (i < NCAND) {
            float sc = cb[i * 8 + 7];
            k = ((u64)__float_as_uint(sc) << 32) | (u64)(0xFFFFFFFFu - (unsigned)i);
        }
        keys[i] = k;
    }
    __syncthreads();

    for (int k = 2; k <= NPAD; k <<= 1) {
        for (int j = k >> 1; j > 0; j >>= 1) {
            #pragma unroll 2
            for (int t = tid; t < NPAD / 2; t += 1024) {
                int i = ((t / j) * (j << 1)) + (t % j);
                int l = i + j;
                u64 a = keys[i], c = keys[l];
                bool desc = ((i & k) == 0);
                if (desc ? (a < c) : (a > c)) { keys[i] = c; keys[l] = a; }
            }
            __syncthreads();
        }
    }

    __shared__ float y0s[TOPK], x0s[TOPK], y1s[TOPK], x1s[TOPK], areas[TOPK];
    __shared__ int labs[TOPK];
    __shared__ int sel[TOPK];
    __shared__ unsigned char keep[TOPK];
    if (tid < TOPK) {
        u64 k = keys[tid];
        int ii = (int)(0xFFFFFFFFu - (unsigned)(k & 0xFFFFFFFFu));
        sel[tid] = ii;
        float y0 = cb[ii * 8 + 0], x0 = cb[ii * 8 + 1];
        float y1 = cb[ii * 8 + 2], x1 = cb[ii * 8 + 3];
        y0s[tid] = y0; x0s[tid] = x0; y1s[tid] = y1; x1s[tid] = x1;
        areas[tid] = (y1 - y0) * (x1 - x0);
        labs[tid] = (int)cb[ii * 8 + 6];
        keep[tid] = ((unsigned)(k >> 32) != 0u) ? 1 : 0;
    }
    __syncthreads();

    for (int j = 0; j < TOPK - 1; j++) {
        if (tid > j && tid < TOPK && keep[j] && keep[tid] && labs[tid] == labs[j]) {
            float ty0 = fmaxf(y0s[tid], y0s[j]);
            float tx0 = fmaxf(x0s[tid], x0s[j]);
            float ty1 = fminf(y1s[tid], y1s[j]);
            float tx1 = fminf(x1s[tid], x1s[j]);
            float ih = fmaxf(ty1 - ty0, 0.f);
            float iw = fmaxf(tx1 - tx0, 0.f);
            float inter = ih * iw;
            float iou = inter / (areas[tid] + areas[j] - inter + 1e-9f);
            if (iou > 0.5f) keep[tid] = 0;
        }
        __syncthreads();
    }

    if (tid < TOPK) {
        float* o = out + ((size_t)b * TOPK + tid) * 7;
        if (keep[tid]) {
            int ii = sel[tid];
            o[0] = y0s[tid]; o[1] = x0s[tid]; o[2] = y1s[tid]; o[3] = x1s[tid];
            o[4] = cb[ii * 8 + 4];
            o[5] = cb[ii * 8 + 5];
            o[6] = (float)labs[tid];
        } else {
            #pragma unroll
            for (int k = 0; k < 7; k++) o[k] = 0.f;
        }
    }
}

// ---------------- launch ----------------
static inline int ceil_div(int a, int b) { return (a + b - 1) / b; }

extern "C" void kernel_launch(void* const* d_in, const int* in_sizes, int n_in,
                              void* d_out, int out_size)
{
    (void)in_sizes; (void)n_in; (void)out_size;
    const float* images = (const float*)d_in[0];
    const float* w1 = (const float*)d_in[1];  const float* b1 = (const float*)d_in[2];
    const float* w2 = (const float*)d_in[3];  const float* b2 = (const float*)d_in[4];
    const float* w3 = (const float*)d_in[5];  const float* b3 = (const float*)d_in[6];
    const float* w4 = (const float*)d_in[7];  const float* b4 = (const float*)d_in[8];
    const float* w5 = (const float*)d_in[9];  const float* b5 = (const float*)d_in[10];
    const float* wh1 = (const float*)d_in[11]; const float* bh1 = (const float*)d_in[12];
    const float* wh2 = (const float*)d_in[13]; const float* bh2 = (const float*)d_in[14];
    float* out = (float*)d_out;

    static float *act1 = nullptr, *act2, *act3, *act4, *act5, *feat1, *feat2, *part, *cand, *wperm;
    if (!act1) {
        cudaGetSymbolAddress((void**)&act1, g_act1);
        cudaGetSymbolAddress((void**)&act2, g_act2);
        cudaGetSymbolAddress((void**)&act3, g_act3);
        cudaGetSymbolAddress((void**)&act4, g_act4);
        cudaGetSymbolAddress((void**)&act5, g_act5);
        cudaGetSymbolAddress((void**)&feat1, g_feat1);
        cudaGetSymbolAddress((void**)&feat2, g_feat2);
        cudaGetSymbolAddress((void**)&part, g_part);
        cudaGetSymbolAddress((void**)&cand, g_cand);
        cudaGetSymbolAddress((void**)&wperm, g_wperm);
    }

    // --- fused weight k-reorder (single launch, all 4 layers)
    const int O2 = 0, O3 = 18432, O4 = 92160, O5 = 387072;
    wperm_all_kernel<<<ceil_div(1566720, 256), 256>>>(w2, w3, w4, w5, wperm);

    // --- L1: 3->32, 416->208  (N = 346112, K = 27), BM=32, 64 thr (no reorder)
    gemm9f_kernel<32, 346112, 27, 32, 1, true, true, false, 3, 416, 416, 208, 208, 64>
        <<<dim3(346112 / 128, 1, 1), 64>>>(w1, images, b1, act1);

    // --- L2: 32->64, 208->104 (N = 86528, K = 288), BM=64, reordered
    gemm9f_kernel<64, 86528, 288, 64, 1, true, false, true, 32, 208, 208, 104, 104, 128>
        <<<dim3(86528 / 128, 1, 1), 128>>>(wperm + O2, act1, b2, act2);

    // --- L3: 64->128, 104->52 (N = 21632, K = 576), BM=64, split-K 2, reordered
    gemm9f_kernel<128, 21632, 576, 64, 2, false, false, true, 64, 104, 104, 52, 52, 128>
        <<<dim3(21632 / 128, 2, 2), 128>>>(wperm + O3, act2, b3, part);
    reduce_kernel<128, 21632, 2, true>
        <<<ceil_div(128 * 21632 / 4, 256), 256>>>(part, b3, act3);

    // --- L4: 128->256, 52->26 (N = 5408, K = 1152), BM=64, split-K 4, reordered
    gemm9f_kernel<256, 5408, 1152, 64, 4, false, false, true, 128, 52, 52, 26, 26, 128>
        <<<dim3(ceil_div(5408, 128), 4, 4), 128>>>(wperm + O4, act3, b4, part);
    reduce_kernel<256, 5408, 4, true>
        <<<ceil_div(256 * 5408 / 4, 256), 256>>>(part, b4, act4);

    // --- head2: 255 x 5408, K = 256, split-K 2
    gemm9_kernel<255, 5408, 256, 128, 128, 2, 256, false>
        <<<dim3(ceil_div(5408, 128), 2, 2), 256>>>(wh2, act4, bh2, part);
    reduce_kernel<255, 5408, 2, false>
        <<<ceil_div(255 * 5408 / 4 + 1, 256), 256>>>(part, bh2, feat2);

    // --- L5: 256->512, 26->13 (N = 1352, K = 2304), BM=64, split-K 8, reordered
    gemm9f_kernel<512, 1352, 2304, 64, 8, false, false, true, 256, 26, 26, 13, 13, 128>
        <<<dim3(ceil_div(1352, 128), 8, 8), 128>>>(wperm + O5, act4, b5, part);
    reduce_kernel<512, 1352, 8, true>
        <<<ceil_div(512 * 1352 / 4, 256), 256>>>(part, b5, act5);

    // --- head1: 255 x 1352, K = 512, split-K 4
    gemm9_kernel<255, 1352, 512, 128, 128, 4, 256, false>
        <<<dim3(ceil_div(1352, 128), 2, 4), 256>>>(wh1, act5, bh1, part);
    reduce_kernel<255, 1352, 4, false>
        <<<ceil_div(255 * 1352 / 4 + 1, 256), 256>>>(part, bh1, feat1);

    // --- decode + nms
    decode_kernel<<<ceil_div(BATCH * NCAND, 256), 256>>>(feat1, feat2, cand);
    nms_kernel<<<BATCH, 1024>>>(cand, out);
}